// round 10
// baseline (speedup 1.0000x reference)
#include <cuda_runtime.h>
#include <math.h>

#define T_TOK 4096
#define NH 1024          // hidden
#define NI 512           // intermediate
#define NE 16            // real experts
#define NSLOT 32         // real + zero slots
#define TOPK 4
#define MAXP 4096        // max pairs per expert (<= T)

#define BM 128
#define BN 64
#define BK 32

// ---- static device scratch (no runtime allocation allowed) ----
__device__ int   g_cnt[NE];
__device__ int   g_tok[NE * MAXP];
__device__ float g_wt [NE * MAXP];
__device__ float g_zw [T_TOK];
__device__ int   g_tk_n[T_TOK];
__device__ int   g_tk_pair[T_TOK * TOPK];
__device__ float g_act [(size_t)NE * MAXP * NI];
__device__ float g_pout[(size_t)NE * MAXP * NH];

// ---------------------------------------------------------------------------
__device__ __forceinline__ unsigned f2tf(float f) {
    unsigned r;
    asm("cvt.rna.tf32.f32 %0, %1;" : "=r"(r) : "f"(f));
    return r;
}

__device__ __forceinline__ void mma_tf32u(float* d, const unsigned* a,
                                          unsigned b0, unsigned b1) {
    asm volatile(
        "mma.sync.aligned.m16n8k8.row.col.f32.tf32.tf32.f32 "
        "{%0,%1,%2,%3}, {%4,%5,%6,%7}, {%8,%9}, {%0,%1,%2,%3};"
        : "+f"(d[0]), "+f"(d[1]), "+f"(d[2]), "+f"(d[3])
        : "r"(a[0]), "r"(a[1]), "r"(a[2]), "r"(a[3]), "r"(b0), "r"(b1));
}

#define CPA(dst, src, sz) \
    asm volatile("cp.async.cg.shared.global [%0], [%1], 16, %2;" \
                 :: "r"(dst), "l"(src), "r"(sz))
#define CPC() asm volatile("cp.async.commit_group;")
#define CPW(n) asm volatile("cp.async.wait_group %0;" :: "n"(n))

__device__ __forceinline__ unsigned sptr(const void* p) {
    return (unsigned)__cvta_generic_to_shared(p);
}

// ---------------------------------------------------------------------------
__global__ void reset_kernel() {
    int i = threadIdx.x;
    if (i < NE) g_cnt[i] = 0;
}

// ---------------------------------------------------------------------------
// Router: one block (256 threads) per token. Writes per-expert pair lists and
// the zero-expert weight; does NOT touch out (combine handles it).
__global__ void router_kernel(const float* __restrict__ x,
                              const float* __restrict__ rw,
                              const float* __restrict__ bias) {
    int t = blockIdx.x;
    __shared__ float sc[NSLOT];
    int tid  = threadIdx.x;
    int slot = tid >> 3;
    int sub  = tid & 7;
    const float* xr = x  + (size_t)t * NH;
    const float* wr = rw + (size_t)slot * NH;

    float acc = 0.f;
    for (int h = sub * 4; h < NH; h += 32) {
        float4 xv = *reinterpret_cast<const float4*>(xr + h);
        float4 wv = *reinterpret_cast<const float4*>(wr + h);
        acc += xv.x * wv.x + xv.y * wv.y + xv.z * wv.z + xv.w * wv.w;
    }
    acc += __shfl_down_sync(0xffffffffu, acc, 4, 8);
    acc += __shfl_down_sync(0xffffffffu, acc, 2, 8);
    acc += __shfl_down_sync(0xffffffffu, acc, 1, 8);
    if (sub == 0) sc[slot] = acc;
    __syncthreads();

    if (tid == 0) {
        float mx = -1e30f;
        for (int i = 0; i < NSLOT; i++) mx = fmaxf(mx, sc[i]);
        float e[NSLOT], sum = 0.f;
        for (int i = 0; i < NSLOT; i++) { e[i] = expf(sc[i] - mx); sum += e[i]; }
        float inv = 1.f / sum;
        float sb[NSLOT];
        for (int i = 0; i < NSLOT; i++) {
            sc[i] = e[i] * inv;
            sb[i] = sc[i] + bias[i];
        }
        float zero_w = 0.f;
        int tkn = 0;
        for (int kk = 0; kk < TOPK; kk++) {
            int bi = 0; float bv = -1e30f;
            for (int i = 0; i < NSLOT; i++)
                if (sb[i] > bv) { bv = sb[i]; bi = i; }
            sb[bi] = -1e30f;
            float w = sc[bi];
            if (bi < NE) {
                int s2 = atomicAdd(&g_cnt[bi], 1);
                g_tok[bi * MAXP + s2] = t;
                g_wt [bi * MAXP + s2] = w;
                g_tk_pair[t * TOPK + tkn] = bi * MAXP + s2;
                tkn++;
            } else {
                zero_w += w;
            }
        }
        g_tk_n[t] = tkn;
        g_zw[t]   = zero_w;
    }
}

// ---------------------------------------------------------------------------
// Smem layouts per stage (BK=32):
//   A: 128r x 32k, word(r,k) = r*32 + (k ^ ((r&7)<<2))       (16KB)
//   B:  32k x 64n, word(k,n) = k*64 + (n ^ ((k&3)<<3))       (8KB)
// cp.async writes and all fragment reads are bank-conflict-free
// (verified lane-by-lane for both patterns).

// gemm1 stage stride (floats): A 4096 + Bg 2048 + Bu 2048
#define ST1 8192
// gemm2 stage stride: A 4096 + B 2048
#define ST2 6144

// ---------------------------------------------------------------------------
// GEMM1: act = silu(X.Wg)*(X.Wu).  Block 128x64, 8 warps (4m x 2n),
// warp tile 32x32 per matrix.  3-stage cp.async pipeline, 96KB dynamic smem.
__global__ __launch_bounds__(256) void gemm1_tc(const float* __restrict__ x,
                                                const float* __restrict__ wg,
                                                const float* __restrict__ wu) {
    int e    = blockIdx.z;
    int cnt  = g_cnt[e];
    int row0 = blockIdx.y * BM;
    if (row0 >= cnt) return;
    int col0 = blockIdx.x * BN;

    extern __shared__ float smem[];

    int tid  = threadIdx.x;
    int lane = tid & 31;
    int wid  = tid >> 5;
    int wm   = wid >> 1;      // 0..3
    int wn   = wid & 1;       // 0..1

    // --- A loader: 4 chunks/thread ---
    int tok[4], lc[4];
    unsigned adst[4];
#pragma unroll
    for (int it = 0; it < 4; it++) {
        int f = tid + 256 * it;
        int r = f >> 3;
        int c = (f & 7) * 4;
        lc[it] = c;
        int rr = row0 + r;
        tok[it] = (rr < cnt) ? g_tok[e * MAXP + rr] : -1;
        adst[it] = r * 32 + (c ^ ((r & 7) << 2));
    }
    // --- B loader: 2 chunks/thread per matrix ---
    int bkrow[2], bc[2];
    unsigned bdst[2];
    const float* wgP[2];
    const float* wuP[2];
#pragma unroll
    for (int it = 0; it < 2; it++) {
        int f = tid + 256 * it;
        int kr = f >> 4;              // 0..31
        int c  = (f & 15) * 4;        // 0..60
        bkrow[it] = kr; bc[it] = c;
        bdst[it] = kr * 64 + (c ^ ((kr & 3) << 3));
        wgP[it] = wg + (size_t)e * NH * NI + (size_t)kr * NI + col0 + c;
        wuP[it] = wu + (size_t)e * NH * NI + (size_t)kr * NI + col0 + c;
    }

    float dg[2][4][4] = {};
    float du[2][4][4] = {};

    const int NIT = NH / BK;  // 32

    // prologue: stages 0,1
#pragma unroll
    for (int s = 0; s < 2; s++) {
        int kb = s * BK;
        float* A  = smem + s * ST1;
        float* Bg = A + 4096;
        float* Bu = A + 6144;
#pragma unroll
        for (int it = 0; it < 4; it++) {
            const float* src = (tok[it] >= 0)
                ? x + (size_t)tok[it] * NH + kb + lc[it] : x;
            CPA(sptr(&A[adst[it]]), src, tok[it] >= 0 ? 16 : 0);
        }
#pragma unroll
        for (int it = 0; it < 2; it++) {
            CPA(sptr(&Bg[bdst[it]]), wgP[it] + (size_t)kb * NI, 16);
            CPA(sptr(&Bu[bdst[it]]), wuP[it] + (size_t)kb * NI, 16);
        }
        CPC();
    }

    int g  = lane >> 2;
    int tg = lane & 3;
    int gx = g << 2;

    int buf = 0;
    for (int kt = 0; kt < NIT; kt++) {
        CPW(1);
        __syncthreads();

        const float* A  = smem + buf * ST1;
        const float* Bg = A + 4096;
        const float* Bu = A + 6144;
#pragma unroll
        for (int k8 = 0; k8 < 4; k8++) {
            int ka  = (k8 * 8 + tg)     ^ gx;
            int ka4 = (k8 * 8 + tg + 4) ^ gx;
            unsigned a[2][4];
#pragma unroll
            for (int m = 0; m < 2; m++) {
                int rw_ = (wm * 32 + m * 16 + g) * 32;
                a[m][0] = f2tf(A[rw_ + ka]);
                a[m][1] = f2tf(A[rw_ + 256 + ka]);
                a[m][2] = f2tf(A[rw_ + ka4]);
                a[m][3] = f2tf(A[rw_ + 256 + ka4]);
            }
            int kb0 = (k8 * 8 + tg) * 64;
            int kb4 = kb0 + 256;
#pragma unroll
            for (int nt = 0; nt < 4; nt++) {
                int nx = (wn * 32 + nt * 8 + g) ^ (tg << 3);
                unsigned g0 = f2tf(Bg[kb0 + nx]);
                unsigned g1 = f2tf(Bg[kb4 + nx]);
                unsigned u0 = f2tf(Bu[kb0 + nx]);
                unsigned u1 = f2tf(Bu[kb4 + nx]);
#pragma unroll
                for (int m = 0; m < 2; m++) {
                    mma_tf32u(dg[m][nt], a[m], g0, g1);
                    mma_tf32u(du[m][nt], a[m], u0, u1);
                }
            }
        }

        int kn = kt + 2;
        if (kn < NIT) {
            int s  = (buf + 2 >= 3) ? buf - 1 : buf + 2;
            int kb = kn * BK;
            float* An = smem + s * ST1;
            float* Bgn = An + 4096;
            float* Bun = An + 6144;
#pragma unroll
            for (int it = 0; it < 4; it++) {
                const float* src = (tok[it] >= 0)
                    ? x + (size_t)tok[it] * NH + kb + lc[it] : x;
                CPA(sptr(&An[adst[it]]), src, tok[it] >= 0 ? 16 : 0);
            }
#pragma unroll
            for (int it = 0; it < 2; it++) {
                CPA(sptr(&Bgn[bdst[it]]), wgP[it] + (size_t)kb * NI, 16);
                CPA(sptr(&Bun[bdst[it]]), wuP[it] + (size_t)kb * NI, 16);
            }
        }
        CPC();
        if (++buf == 3) buf = 0;
    }

    // epilogue: silu(g)*u
    size_t base = (size_t)e * MAXP;
    int cg = lane >> 2, ct = lane & 3;
#pragma unroll
    for (int m = 0; m < 2; m++) {
        int rb = row0 + wm * 32 + m * 16 + cg;
#pragma unroll
        for (int n = 0; n < 4; n++) {
            int cb = col0 + wn * 32 + n * 8 + 2 * ct;
            if (rb < cnt) {
                float gv0 = dg[m][n][0], gv1 = dg[m][n][1];
                float s0 = gv0 / (1.f + expf(-gv0));
                float s1 = gv1 / (1.f + expf(-gv1));
                float2 o = make_float2(s0 * du[m][n][0], s1 * du[m][n][1]);
                *reinterpret_cast<float2*>(&g_act[(base + rb) * NI + cb]) = o;
            }
            if (rb + 8 < cnt) {
                float gv2 = dg[m][n][2], gv3 = dg[m][n][3];
                float s2 = gv2 / (1.f + expf(-gv2));
                float s3 = gv3 / (1.f + expf(-gv3));
                float2 o = make_float2(s2 * du[m][n][2], s3 * du[m][n][3]);
                *reinterpret_cast<float2*>(&g_act[(base + rb + 8) * NI + cb]) = o;
            }
        }
    }
}

// ---------------------------------------------------------------------------
// GEMM2: pout = wt * (act . w_down).  Block 128x64, 3-stage pipeline (72KB).
__global__ __launch_bounds__(256) void gemm2_tc(const float* __restrict__ wd) {
    int e    = blockIdx.z;
    int cnt  = g_cnt[e];
    int row0 = blockIdx.y * BM;
    if (row0 >= cnt) return;
    int col0 = blockIdx.x * BN;

    extern __shared__ float smem[];

    int tid  = threadIdx.x;
    int lane = tid & 31;
    int wid  = tid >> 5;
    int wm   = wid >> 1;
    int wn   = wid & 1;

    size_t pbase = (size_t)e * MAXP;

    int lc[4];
    bool aval[4];
    unsigned adst[4];
    const float* aptr[4];
#pragma unroll
    for (int it = 0; it < 4; it++) {
        int f = tid + 256 * it;
        int r = f >> 3;
        int c = (f & 7) * 4;
        lc[it] = c;
        aval[it] = (row0 + r) < cnt;
        aptr[it] = &g_act[(pbase + row0 + r) * NI + c];
        adst[it] = r * 32 + (c ^ ((r & 7) << 2));
    }
    unsigned bdst[2];
    const float* wdP[2];
#pragma unroll
    for (int it = 0; it < 2; it++) {
        int f = tid + 256 * it;
        int kr = f >> 4;
        int c  = (f & 15) * 4;
        bdst[it] = kr * 64 + (c ^ ((kr & 3) << 3));
        wdP[it] = wd + (size_t)e * NI * NH + (size_t)kr * NH + col0 + c;
    }

    float d[2][4][4] = {};

    const int NIT = NI / BK;  // 16

    // prologue: stages 0,1
#pragma unroll
    for (int s = 0; s < 2; s++) {
        int kb = s * BK;
        float* A = smem + s * ST2;
        float* B = A + 4096;
#pragma unroll
        for (int it = 0; it < 4; it++) {
            const float* src = aval[it] ? aptr[it] + kb : &g_act[0];
            CPA(sptr(&A[adst[it]]), src, aval[it] ? 16 : 0);
        }
#pragma unroll
        for (int it = 0; it < 2; it++)
            CPA(sptr(&B[bdst[it]]), wdP[it] + (size_t)kb * NH, 16);
        CPC();
    }

    int g  = lane >> 2;
    int tg = lane & 3;
    int gx = g << 2;

    int buf = 0;
    for (int kt = 0; kt < NIT; kt++) {
        CPW(1);
        __syncthreads();

        const float* A = smem + buf * ST2;
        const float* B = A + 4096;
#pragma unroll
        for (int k8 = 0; k8 < 4; k8++) {
            int ka  = (k8 * 8 + tg)     ^ gx;
            int ka4 = (k8 * 8 + tg + 4) ^ gx;
            unsigned a[2][4];
#pragma unroll
            for (int m = 0; m < 2; m++) {
                int rw_ = (wm * 32 + m * 16 + g) * 32;
                a[m][0] = f2tf(A[rw_ + ka]);
                a[m][1] = f2tf(A[rw_ + 256 + ka]);
                a[m][2] = f2tf(A[rw_ + ka4]);
                a[m][3] = f2tf(A[rw_ + 256 + ka4]);
            }
            int kb0 = (k8 * 8 + tg) * 64;
            int kb4 = kb0 + 256;
#pragma unroll
            for (int nt = 0; nt < 4; nt++) {
                int nx = (wn * 32 + nt * 8 + g) ^ (tg << 3);
                unsigned b0 = f2tf(B[kb0 + nx]);
                unsigned b1 = f2tf(B[kb4 + nx]);
#pragma unroll
                for (int m = 0; m < 2; m++)
                    mma_tf32u(d[m][nt], a[m], b0, b1);
            }
        }

        int kn = kt + 2;
        if (kn < NIT) {
            int s  = (buf + 2 >= 3) ? buf - 1 : buf + 2;
            int kb = kn * BK;
            float* An = smem + s * ST2;
            float* Bn = An + 4096;
#pragma unroll
            for (int it = 0; it < 4; it++) {
                const float* src = aval[it] ? aptr[it] + kb : &g_act[0];
                CPA(sptr(&An[adst[it]]), src, aval[it] ? 16 : 0);
            }
#pragma unroll
            for (int it = 0; it < 2; it++)
                CPA(sptr(&Bn[bdst[it]]), wdP[it] + (size_t)kb * NH, 16);
        }
        CPC();
        if (++buf == 3) buf = 0;
    }

    int cg = lane >> 2, ct = lane & 3;
#pragma unroll
    for (int m = 0; m < 2; m++) {
        int rb = row0 + wm * 32 + m * 16 + cg;
        float w0 = (rb     < cnt) ? g_wt[e * MAXP + rb]     : 0.f;
        float w1 = (rb + 8 < cnt) ? g_wt[e * MAXP + rb + 8] : 0.f;
#pragma unroll
        for (int n = 0; n < 4; n++) {
            int cb = col0 + wn * 32 + n * 8 + 2 * ct;
            if (rb < cnt) {
                float2 o = make_float2(d[m][n][0] * w0, d[m][n][1] * w0);
                *reinterpret_cast<float2*>(&g_pout[(pbase + rb) * NH + cb]) = o;
            }
            if (rb + 8 < cnt) {
                float2 o = make_float2(d[m][n][2] * w1, d[m][n][3] * w1);
                *reinterpret_cast<float2*>(&g_pout[(pbase + rb + 8) * NH + cb]) = o;
            }
        }
    }
}

// ---------------------------------------------------------------------------
// Combine: out[t] = zw*x[t] + sum of this token's pair outputs (topk order).
__global__ void combine_kernel(const float* __restrict__ x,
                               float* __restrict__ out) {
    int t  = blockIdx.x;
    int np = g_tk_n[t];
    int p[TOPK];
    for (int j = 0; j < np; j++) p[j] = g_tk_pair[t * TOPK + j];
    float zw = g_zw[t];
    int h4 = threadIdx.x;
    float4 xv = *reinterpret_cast<const float4*>(&x[(size_t)t * NH + h4 * 4]);
    float4 s = make_float4(zw * xv.x, zw * xv.y, zw * xv.z, zw * xv.w);
    for (int j = 0; j < np; j++) {
        float4 v = *reinterpret_cast<const float4*>(&g_pout[(size_t)p[j] * NH + h4 * 4]);
        s.x += v.x; s.y += v.y; s.z += v.z; s.w += v.w;
    }
    *reinterpret_cast<float4*>(&out[(size_t)t * NH + h4 * 4]) = s;
}

// ---------------------------------------------------------------------------
extern "C" void kernel_launch(void* const* d_in, const int* in_sizes, int n_in,
                              void* d_out, int out_size) {
    (void)in_sizes; (void)n_in; (void)out_size;
    const float* x    = (const float*)d_in[0];
    const float* rw   = (const float*)d_in[1];
    const float* bias = (const float*)d_in[2];
    const float* wg   = (const float*)d_in[3];
    const float* wu   = (const float*)d_in[4];
    const float* wd   = (const float*)d_in[5];
    float* out = (float*)d_out;

    static bool attr_set = false;
    if (!attr_set) {
        cudaFuncSetAttribute(gemm1_tc, cudaFuncAttributeMaxDynamicSharedMemorySize,
                             3 * ST1 * 4);
        cudaFuncSetAttribute(gemm2_tc, cudaFuncAttributeMaxDynamicSharedMemorySize,
                             3 * ST2 * 4);
        attr_set = true;
    }

    reset_kernel<<<1, 32>>>();
    router_kernel<<<T_TOK, 256>>>(x, rw, bias);

    dim3 g1(NI / BN, MAXP / BM, NE);
    gemm1_tc<<<g1, 256, 3 * ST1 * 4>>>(x, wg, wu);

    dim3 g2(NH / BN, MAXP / BM, NE);
    gemm2_tc<<<g2, 256, 3 * ST2 * 4>>>(wd);

    combine_kernel<<<T_TOK, 256>>>(x, out);
}